// round 10
// baseline (speedup 1.0000x reference)
#include <cuda_runtime.h>
#include <cuda_fp16.h>
#include <cstdint>

#define NB   32
#define LA   512
#define LB   512
#define DIM  768
#define OUTC 3072
#define NROW (NB*512)

// ---------------- scratch (__device__ globals; no allocation allowed) -------
__device__ __align__(1024) __half g_ah [(size_t)NB*LA*DIM], g_al [(size_t)NB*LA*DIM];
__device__ __align__(1024) __half g_bh [(size_t)NB*LB*DIM], g_bl [(size_t)NB*LB*DIM];
__device__ __align__(1024) __half g_aTh[(size_t)NB*DIM*LA];
__device__ __align__(1024) __half g_bTh[(size_t)NB*DIM*LB];
__device__ __align__(1024) float g_e[(size_t)NB*LA*LB];
__device__ float g_rpmax[4*NROW], g_rpsum[4*NROW];   // row partials: 4 col-blocks
__device__ float g_cpmax[2*NROW], g_cpsum[2*NROW];   // col partials: 2 row-blocks
__device__ float g_rowm[NROW], g_rowi[NROW], g_colm[NROW], g_coli[NROW];

// ---------------- low-level helpers (portable PTX only) ---------------------
__device__ __forceinline__ uint32_t smem_to_u32(const void* p) {
    uint32_t a;
    asm("{ .reg .u64 t; cvta.to.shared.u64 t, %1; cvt.u32.u64 %0, t; }" : "=r"(a) : "l"(p));
    return a;
}
__device__ __forceinline__ void cp16(uint32_t dst, const void* src) {
    asm volatile("cp.async.cg.shared.global [%0], [%1], 16;" :: "r"(dst), "l"(src));
}
__device__ __forceinline__ void cp_commit() { asm volatile("cp.async.commit_group;"); }
__device__ __forceinline__ void cp_wait1()  { asm volatile("cp.async.wait_group 1;"); }
__device__ __forceinline__ void cp_wait0()  { asm volatile("cp.async.wait_group 0;"); }

__device__ __forceinline__ void ldsm4(uint32_t* r, uint32_t addr) {
    asm volatile("ldmatrix.sync.aligned.m8n8.x4.shared.b16 {%0,%1,%2,%3}, [%4];"
                 : "=r"(r[0]), "=r"(r[1]), "=r"(r[2]), "=r"(r[3]) : "r"(addr));
}
__device__ __forceinline__ void mma_f16(float* c, const uint32_t* a, const uint32_t* b) {
    asm volatile("mma.sync.aligned.m16n8k16.row.col.f32.f16.f16.f32 "
                 "{%0,%1,%2,%3}, {%4,%5,%6,%7}, {%8,%9}, {%0,%1,%2,%3};"
                 : "+f"(c[0]), "+f"(c[1]), "+f"(c[2]), "+f"(c[3])
                 : "r"(a[0]), "r"(a[1]), "r"(a[2]), "r"(a[3]), "r"(b[0]), "r"(b[1]));
}

__device__ __forceinline__ uint32_t sw_off(int row, int kh) {
    return (uint32_t)(row * 32 + ((kh ^ ((row >> 2) & 1)) << 4));
}

// =============================================================================
// GEMM1: e = (Ah+Al)(Bh+Bl)^T. CTA tile 256(M)x128(N), 512 thr, 16 warps 4x4.
// Warp tile 64x32. 3 passes f32 acc. Stores e + row/col partial stats.
// =============================================================================
#define A_TILE1 16384        // 256 rows x 32 halfs
#define B_TILE1 8192         // 128 rows x 32 halfs
#define G1_STAGE (2*A_TILE1 + 2*B_TILE1)    // 49152
#define G1_SCRATCH 16384
#define G1_SMEM (2*G1_STAGE + G1_SCRATCH + 1024)

__global__ __launch_bounds__(512)
void gemm1_k(const __half* __restrict__ Ah, const __half* __restrict__ Al,
             const __half* __restrict__ Bh, const __half* __restrict__ Bl,
             float* __restrict__ E)
{
    extern __shared__ char smraw[];
    uint32_t sm0 = smem_to_u32(smraw);
    uint32_t smb = (sm0 + 1023u) & ~1023u;
    char* smc = smraw + (smb - sm0);

    const int tid = threadIdx.x;
    const int lid = tid & 31, wid = tid >> 5;
    const int wm = wid >> 2, wn = wid & 3;          // 4 x 4 warp grid
    const int g = lid >> 2, t = lid & 3;
    const int z = blockIdx.z, m0 = blockIdx.y * 256, n0 = blockIdx.x * 128;
    const int K = DIM;

    const __half* srcA[2] = { Ah + ((size_t)z * LA + m0) * K,
                              Al + ((size_t)z * LA + m0) * K };
    const __half* srcB[2] = { Bh + ((size_t)z * LB + n0) * K,
                              Bl + ((size_t)z * LB + n0) * K };

    const int ar  = (lid & 7) | (((lid >> 3) & 1) << 3);
    const int akh = lid >> 4;
    uint32_t aoff[4];
    #pragma unroll
    for (int i = 0; i < 4; i++)
        aoff[i] = sw_off(wm * 64 + i * 16 + ar, akh);
    const int br  = (lid & 7) | ((lid >> 4) << 3);
    const int bkh = (lid >> 3) & 1;
    uint32_t boff[2];
    #pragma unroll
    for (int j2 = 0; j2 < 2; j2++)
        boff[j2] = sw_off(wn * 32 + j2 * 16 + br, bkh);

    float acc[4][4][4];
    #pragma unroll
    for (int i = 0; i < 4; i++)
        #pragma unroll
        for (int j = 0; j < 4; j++)
            #pragma unroll
            for (int r = 0; r < 4; r++) acc[i][j][r] = 0.f;

    const int nk = K >> 5;

    auto issue_stage = [&](int s, int kt) {
        uint32_t sb = smb + s * G1_STAGE;
        // A tiles: 2 x 1024 16B-chunks
        #pragma unroll
        for (int tl = 0; tl < 2; tl++) {
            #pragma unroll
            for (int it = 0; it < 2; it++) {
                int idx = tid + it * 512;
                int m = idx >> 2, ks = (idx >> 1) & 1, kh = idx & 1;
                cp16(sb + tl * A_TILE1 + ks * 8192 + sw_off(m, kh),
                     srcA[tl] + (size_t)m * K + kt * 32 + ks * 16 + kh * 8);
            }
        }
        // B tiles: 2 x 512 chunks
        #pragma unroll
        for (int tl = 0; tl < 2; tl++) {
            int m = tid >> 2, ks = (tid >> 1) & 1, kh = tid & 1;
            cp16(sb + 2 * A_TILE1 + tl * B_TILE1 + ks * 4096 + sw_off(m, kh),
                 srcB[tl] + (size_t)m * K + kt * 32 + ks * 16 + kh * 8);
        }
    };

    issue_stage(0, 0);
    cp_commit();

    for (int kt = 0; kt < nk; kt++) {
        if (kt + 1 < nk) { issue_stage((kt + 1) & 1, kt + 1); }
        cp_commit();
        cp_wait1();
        __syncthreads();

        uint32_t st = smb + (kt & 1) * G1_STAGE;
        #pragma unroll
        for (int ks = 0; ks < 2; ks++) {
            uint32_t b_h[4][2], b_l[4][2];
            #pragma unroll
            for (int j2 = 0; j2 < 2; j2++) {
                uint32_t rh[4], rl[4];
                ldsm4(rh, st + 2 * A_TILE1 + 0 * B_TILE1 + ks * 4096 + boff[j2]);
                ldsm4(rl, st + 2 * A_TILE1 + 1 * B_TILE1 + ks * 4096 + boff[j2]);
                b_h[j2*2+0][0] = rh[0]; b_h[j2*2+0][1] = rh[1];
                b_h[j2*2+1][0] = rh[2]; b_h[j2*2+1][1] = rh[3];
                b_l[j2*2+0][0] = rl[0]; b_l[j2*2+0][1] = rl[1];
                b_l[j2*2+1][0] = rl[2]; b_l[j2*2+1][1] = rl[3];
            }
            // hh + hl with a_h live, then lh with a_l (keeps reg pressure low)
            {
                uint32_t a_h[4][4];
                #pragma unroll
                for (int i = 0; i < 4; i++)
                    ldsm4(a_h[i], st + 0 * A_TILE1 + ks * 8192 + aoff[i]);
                #pragma unroll
                for (int i = 0; i < 4; i++)
                    #pragma unroll
                    for (int j = 0; j < 4; j++) {
                        mma_f16(acc[i][j], a_h[i], b_h[j]);
                        mma_f16(acc[i][j], a_h[i], b_l[j]);
                    }
            }
            {
                uint32_t a_l[4][4];
                #pragma unroll
                for (int i = 0; i < 4; i++)
                    ldsm4(a_l[i], st + 1 * A_TILE1 + ks * 8192 + aoff[i]);
                #pragma unroll
                for (int i = 0; i < 4; i++)
                    #pragma unroll
                    for (int j = 0; j < 4; j++)
                        mma_f16(acc[i][j], a_l[i], b_h[j]);
            }
        }
        __syncthreads();
    }

    // ---- store e (fp32) ----
    #pragma unroll
    for (int i = 0; i < 4; i++)
        #pragma unroll
        for (int j = 0; j < 4; j++) {
            int n = n0 + wn * 32 + j * 8 + t * 2;
            #pragma unroll
            for (int h = 0; h < 2; h++) {
                int m = m0 + wm * 64 + i * 16 + g + h * 8;
                *(float2*)(E + ((size_t)z * LA + m) * LB + n) =
                    make_float2(acc[i][j][h*2+0], acc[i][j][h*2+1]);
            }
        }

    // ---- partial row/col softmax stats ----
    __syncthreads();
    float* scr   = (float*)(smc + 2 * G1_STAGE);
    float* srmax = scr;            // [256][4]
    float* srsum = scr + 1024;     // [256][4]
    float* srm   = scr + 2048;     // [256]
    float* scmax = scr + 2304;     // [128][4]
    float* scsum = scr + 2816;     // [128][4]
    float* scm   = scr + 3328;     // [128]

    // row partial max (reduce over j, t)
    #pragma unroll
    for (int i = 0; i < 4; i++)
        #pragma unroll
        for (int h = 0; h < 2; h++) {
            float mv = -3.4e38f;
            #pragma unroll
            for (int j = 0; j < 4; j++) {
                mv = fmaxf(mv, acc[i][j][h*2+0]);
                mv = fmaxf(mv, acc[i][j][h*2+1]);
            }
            mv = fmaxf(mv, __shfl_xor_sync(0xFFFFFFFFu, mv, 1));
            mv = fmaxf(mv, __shfl_xor_sync(0xFFFFFFFFu, mv, 2));
            if (t == 0) srmax[(wm*64 + i*16 + g + h*8) * 4 + wn] = mv;
        }
    __syncthreads();
    if (tid < 256)
        srm[tid] = fmaxf(fmaxf(srmax[tid*4+0], srmax[tid*4+1]),
                         fmaxf(srmax[tid*4+2], srmax[tid*4+3]));
    __syncthreads();
    #pragma unroll
    for (int i = 0; i < 4; i++)
        #pragma unroll
        for (int h = 0; h < 2; h++) {
            int row = wm*64 + i*16 + g + h*8;
            float rm = srm[row], s = 0.f;
            #pragma unroll
            for (int j = 0; j < 4; j++) {
                s += __expf(acc[i][j][h*2+0] - rm);
                s += __expf(acc[i][j][h*2+1] - rm);
            }
            s += __shfl_xor_sync(0xFFFFFFFFu, s, 1);
            s += __shfl_xor_sync(0xFFFFFFFFu, s, 2);
            if (t == 0) srsum[row * 4 + wn] = s;
        }
    __syncthreads();
    if (tid < 256) {
        size_t o = (size_t)blockIdx.x * NROW + z * 512 + m0 + tid;
        g_rpmax[o] = srm[tid];
        g_rpsum[o] = srsum[tid*4+0] + srsum[tid*4+1] + srsum[tid*4+2] + srsum[tid*4+3];
    }

    // col partial max (reduce over i, g)
    #pragma unroll
    for (int j = 0; j < 4; j++)
        #pragma unroll
        for (int rl = 0; rl < 2; rl++) {
            float mv = -3.4e38f;
            #pragma unroll
            for (int i = 0; i < 4; i++) {
                mv = fmaxf(mv, acc[i][j][rl]);
                mv = fmaxf(mv, acc[i][j][2+rl]);
            }
            mv = fmaxf(mv, __shfl_xor_sync(0xFFFFFFFFu, mv, 4));
            mv = fmaxf(mv, __shfl_xor_sync(0xFFFFFFFFu, mv, 8));
            mv = fmaxf(mv, __shfl_xor_sync(0xFFFFFFFFu, mv, 16));
            if (g == 0) scmax[(wn*32 + j*8 + t*2 + rl) * 4 + wm] = mv;
        }
    __syncthreads();
    if (tid < 128)
        scm[tid] = fmaxf(fmaxf(scmax[tid*4+0], scmax[tid*4+1]),
                         fmaxf(scmax[tid*4+2], scmax[tid*4+3]));
    __syncthreads();
    #pragma unroll
    for (int j = 0; j < 4; j++)
        #pragma unroll
        for (int rl = 0; rl < 2; rl++) {
            int col = wn*32 + j*8 + t*2 + rl;
            float cm = scm[col], s = 0.f;
            #pragma unroll
            for (int i = 0; i < 4; i++) {
                s += __expf(acc[i][j][rl] - cm);
                s += __expf(acc[i][j][2+rl] - cm);
            }
            s += __shfl_xor_sync(0xFFFFFFFFu, s, 4);
            s += __shfl_xor_sync(0xFFFFFFFFu, s, 8);
            s += __shfl_xor_sync(0xFFFFFFFFu, s, 16);
            if (g == 0) scsum[col * 4 + wm] = s;
        }
    __syncthreads();
    if (tid < 128) {
        size_t o = (size_t)blockIdx.y * NROW + z * 512 + n0 + tid;
        g_cpmax[o] = scm[tid];
        g_cpsum[o] = scsum[tid*4+0] + scsum[tid*4+1] + scsum[tid*4+2] + scsum[tid*4+3];
    }
}

// ---------------- reduce partials -> max + 1/sum -----------------------------
__global__ __launch_bounds__(256)
void reduce_stats_k()
{
    int idx = blockIdx.x * 256 + threadIdx.x;
    if (blockIdx.y) {   // col: 2 partials
        float m = fmaxf(g_cpmax[idx], g_cpmax[NROW + idx]);
        float s = g_cpsum[idx] * __expf(g_cpmax[idx] - m)
                + g_cpsum[NROW + idx] * __expf(g_cpmax[NROW + idx] - m);
        g_colm[idx] = m; g_coli[idx] = 1.f / s;
    } else {            // row: 4 partials
        float m = -3.4e38f;
        #pragma unroll
        for (int p = 0; p < 4; p++) m = fmaxf(m, g_rpmax[p * NROW + idx]);
        float s = 0.f;
        #pragma unroll
        for (int p = 0; p < 4; p++)
            s += g_rpsum[p * NROW + idx] * __expf(g_rpmax[p * NROW + idx] - m);
        g_rowm[idx] = m; g_rowi[idx] = 1.f / s;
    }
}

// =============================================================================
// GEMM_PV: C = P Bh^T, CTA tile 128(M)x256(N), 512 thr, warps 4x4 (32x64 each).
// Single fp16 pass, on-the-fly P from e.
// =============================================================================
#define A_TILEP 8192         // 128 rows x 32 halfs
#define B_TILEP 16384        // 256 rows x 32 halfs
#define PV_STAGE (A_TILEP + B_TILEP)        // 24576
#define PV_SMEM (2*PV_STAGE + 2048)

template<bool TRANSA>
__global__ __launch_bounds__(512)
void gemm_pv(const float* __restrict__ E,
             const float* __restrict__ Msc, const float* __restrict__ Isc,
             const __half* __restrict__ Bh,
             const float* __restrict__ Obase, float* __restrict__ Out)
{
    const int M = 512, N = DIM, K = 512;
    extern __shared__ char smraw[];
    uint32_t sm0 = smem_to_u32(smraw);
    uint32_t smb = (sm0 + 1023u) & ~1023u;
    char* smc = smraw + (smb - sm0);

    const int tid = threadIdx.x;
    const int lid = tid & 31, wid = tid >> 5;
    const int wm = wid >> 2, wn = wid & 3;
    const int z = blockIdx.z, m0 = blockIdx.y * 128, n0 = blockIdx.x * 256;

    float* sm_m = (float*)(smc + 2 * PV_STAGE);
    float* sm_i = sm_m + 128;
    if (tid < 128) {
        sm_m[tid] = Msc[z * 512 + m0 + tid];
        sm_i[tid] = Isc[z * 512 + m0 + tid];
    }

    const __half* srcB = Bh + ((size_t)z * N + n0) * K;

    const int ar  = (lid & 7) | (((lid >> 3) & 1) << 3);
    const int akh = lid >> 4;
    uint32_t aoff[2];
    #pragma unroll
    for (int i = 0; i < 2; i++)
        aoff[i] = sw_off(wm * 32 + i * 16 + ar, akh);
    const int br  = (lid & 7) | ((lid >> 4) << 3);
    const int bkh = (lid >> 3) & 1;
    uint32_t boff[4];
    #pragma unroll
    for (int j2 = 0; j2 < 4; j2++)
        boff[j2] = sw_off(wn * 64 + j2 * 16 + br, bkh);

    float acc[2][8][4];
    #pragma unroll
    for (int i = 0; i < 2; i++)
        #pragma unroll
        for (int j = 0; j < 8; j++)
            #pragma unroll
            for (int r = 0; r < 4; r++) acc[i][j][r] = 0.f;

    const int nk = K >> 5;   // 16

    auto issueB = [&](int s, int kt) {
        uint32_t tb = smb + s * PV_STAGE + A_TILEP;
        #pragma unroll
        for (int it = 0; it < 2; it++) {
            int idx = tid + it * 512;
            int m = idx >> 2, ks = (idx >> 1) & 1, kh = idx & 1;
            cp16(tb + ks * 8192 + sw_off(m, kh),
                 srcB + (size_t)m * K + kt * 32 + ks * 16 + kh * 8);
        }
    };

    auto fillA = [&](int s, int kt) {
        char* tb = smc + s * PV_STAGE;
        if (!TRANSA) {
            int row = tid >> 2, kc = tid & 3;
            const float* ep = E + ((size_t)z * M + m0 + row) * K + kt * 32 + kc * 8;
            float4 v0 = *(const float4*)(ep);
            float4 v1 = *(const float4*)(ep + 4);
            float rm = sm_m[row], ri = sm_i[row];
            __half2 h0 = __floats2half2_rn(__expf(v0.x - rm) * ri, __expf(v0.y - rm) * ri);
            __half2 h1 = __floats2half2_rn(__expf(v0.z - rm) * ri, __expf(v0.w - rm) * ri);
            __half2 h2 = __floats2half2_rn(__expf(v1.x - rm) * ri, __expf(v1.y - rm) * ri);
            __half2 h3 = __floats2half2_rn(__expf(v1.z - rm) * ri, __expf(v1.w - rm) * ri);
            uint32_t off = (uint32_t)((kc >> 1) * 4096) + sw_off(row, kc & 1);
            uint4 pk;
            pk.x = *(uint32_t*)&h0; pk.y = *(uint32_t*)&h1;
            pk.z = *(uint32_t*)&h2; pk.w = *(uint32_t*)&h3;
            *(uint4*)(tb + off) = pk;
        } else {
            int col = tid & 127, kc = tid >> 7;
            float cm = sm_m[col], ci = sm_i[col];
            float p[8];
            #pragma unroll
            for (int ik = 0; ik < 8; ik++) {
                float v = E[((size_t)z * 512 + kt * 32 + kc * 8 + ik) * 512 + m0 + col];
                p[ik] = __expf(v - cm) * ci;
            }
            __half2 h0 = __floats2half2_rn(p[0], p[1]);
            __half2 h1 = __floats2half2_rn(p[2], p[3]);
            __half2 h2 = __floats2half2_rn(p[4], p[5]);
            __half2 h3 = __floats2half2_rn(p[6], p[7]);
            uint32_t off = (uint32_t)((kc >> 1) * 4096) + sw_off(col, kc & 1);
            uint4 pk;
            pk.x = *(uint32_t*)&h0; pk.y = *(uint32_t*)&h1;
            pk.z = *(uint32_t*)&h2; pk.w = *(uint32_t*)&h3;
            *(uint4*)(tb + off) = pk;
        }
    };

    issueB(0, 0);
    cp_commit();
    __syncthreads();          // sm_m/sm_i ready
    fillA(0, 0);

    for (int kt = 0; kt < nk; kt++) {
        int s = kt & 1;
        if (kt + 1 < nk) { issueB(s ^ 1, kt + 1); cp_commit(); cp_wait1(); }
        else             { cp_wait0(); }
        __syncthreads();

        uint32_t st = smb + s * PV_STAGE;
        #pragma unroll
        for (int ks = 0; ks < 2; ks++) {
            uint32_t a_f[2][4], b_h[8][2];
            #pragma unroll
            for (int i = 0; i < 2; i++)
                ldsm4(a_f[i], st + ks * 4096 + aoff[i]);
            #pragma unroll
            for (int j2 = 0; j2 < 4; j2++) {
                uint32_t rh[4];
                ldsm4(rh, st + A_TILEP + ks * 8192 + boff[j2]);
                b_h[j2*2+0][0] = rh[0]; b_h[j2*2+0][1] = rh[1];
                b_h[j2*2+1][0] = rh[2]; b_h[j2*2+1][1] = rh[3];
            }
            #pragma unroll
            for (int i = 0; i < 2; i++)
                #pragma unroll
                for (int j = 0; j < 8; j++)
                    mma_f16(acc[i][j], a_f[i], b_h[j]);
        }
        if (kt + 1 < nk) fillA(s ^ 1, kt + 1);
        __syncthreads();
    }

    // ---- ESIM epilogue ----
    const int g = lid >> 2, t = lid & 3;
    #pragma unroll
    for (int i = 0; i < 2; i++)
        #pragma unroll
        for (int j = 0; j < 8; j++) {
            int n = n0 + wn * 64 + j * 8 + t * 2;
            #pragma unroll
            for (int h = 0; h < 2; h++) {
                int m = m0 + wm * 32 + i * 16 + g + h * 8;
                float2 v = make_float2(acc[i][j][h*2+0], acc[i][j][h*2+1]);
                float2 av = *(const float2*)(Obase + ((size_t)z * M + m) * DIM + n);
                float* orow = Out + ((size_t)z * M + m) * OUTC + n;
                *(float2*)(orow)         = av;
                *(float2*)(orow + DIM)   = v;
                *(float2*)(orow + 2*DIM) = make_float2(av.x - v.x, av.y - v.y);
                *(float2*)(orow + 3*DIM) = make_float2(av.x * v.x, av.y * v.y);
            }
        }
}

// ---------------- fp16 split (+ hi transpose) of fp32 input -----------------
__global__ __launch_bounds__(256)
void conv_split_T(const float* __restrict__ X,
                  __half* __restrict__ Xh,  __half* __restrict__ Xl,
                  __half* __restrict__ XTh, int R, int C)
{
    __shared__ __half sh[64][65];
    int z = blockIdx.z, r0 = blockIdx.y * 64, c0 = blockIdx.x * 64;
    #pragma unroll
    for (int it = 0; it < 16; it++) {
        int idx = threadIdx.x + it * 256;
        int i = idx >> 6, j = idx & 63;
        float v = X[((size_t)z * R + r0 + i) * C + c0 + j];
        __half h = __float2half_rn(v);
        __half l = __float2half_rn(v - __half2float(h));
        Xh[((size_t)z * R + r0 + i) * C + c0 + j] = h;
        Xl[((size_t)z * R + r0 + i) * C + c0 + j] = l;
        sh[i][j] = h;
    }
    __syncthreads();
    #pragma unroll
    for (int it = 0; it < 16; it++) {
        int idx = threadIdx.x + it * 256;
        int j = idx >> 6, i = idx & 63;
        XTh[((size_t)z * C + c0 + j) * R + r0 + i] = sh[i][j];
    }
}

// ---------------------------------------------------------------------------
extern "C" void kernel_launch(void* const* d_in, const int* in_sizes, int n_in,
                              void* d_out, int out_size)
{
    const float* a_bar = (const float*)d_in[0];
    const float* b_bar = (const float*)d_in[1];
    float* out = (float*)d_out;
    float* m_a = out;
    float* m_b = out + (size_t)NB * LA * OUTC;

    __half *ah, *al, *bh, *bl, *aTh, *bTh;
    float *pe, *prm, *pri, *pcm, *pci;
    cudaGetSymbolAddress((void**)&ah,  g_ah);   cudaGetSymbolAddress((void**)&al,  g_al);
    cudaGetSymbolAddress((void**)&bh,  g_bh);   cudaGetSymbolAddress((void**)&bl,  g_bl);
    cudaGetSymbolAddress((void**)&aTh, g_aTh);  cudaGetSymbolAddress((void**)&bTh, g_bTh);
    cudaGetSymbolAddress((void**)&pe,  g_e);
    cudaGetSymbolAddress((void**)&prm, g_rowm); cudaGetSymbolAddress((void**)&pri, g_rowi);
    cudaGetSymbolAddress((void**)&pcm, g_colm); cudaGetSymbolAddress((void**)&pci, g_coli);

    cudaFuncSetAttribute(gemm1_k, cudaFuncAttributeMaxDynamicSharedMemorySize, G1_SMEM);
    cudaFuncSetAttribute(gemm_pv<false>, cudaFuncAttributeMaxDynamicSharedMemorySize, PV_SMEM);
    cudaFuncSetAttribute(gemm_pv<true>,  cudaFuncAttributeMaxDynamicSharedMemorySize, PV_SMEM);

    // 1) fp16 split + transposed hi copies of inputs
    conv_split_T<<<dim3(DIM/64, LA/64, NB), 256>>>(a_bar, ah, al, aTh, LA, DIM);
    conv_split_T<<<dim3(DIM/64, LB/64, NB), 256>>>(b_bar, bh, bl, bTh, LB, DIM);

    // 2) e = a @ b^T + partial softmax stats (256x128 tiles)
    gemm1_k<<<dim3(LB/128, LA/256, NB), 512, G1_SMEM>>>(ah, al, bh, bl, pe);

    // 3) reduce partials
    reduce_stats_k<<<dim3(NROW/256, 2), 256>>>();

    // 4) m_a: softmax_row(e) @ b (128x256 tiles)
    gemm_pv<false><<<dim3(DIM/256, LA/128, NB), 512, PV_SMEM>>>(
        pe, prm, pri, bTh, a_bar, m_a);

    // 5) m_b: softmax_col(e)^T @ a (128x256 tiles)
    gemm_pv<true><<<dim3(DIM/256, LB/128, NB), 512, PV_SMEM>>>(
        pe, pcm, pci, aTh, b_bar, m_b);
}

// round 11
// speedup vs baseline: 1.1341x; 1.1341x over previous
#include <cuda_runtime.h>
#include <cuda_fp16.h>
#include <cstdint>

#define NB   32
#define LA   512
#define LB   512
#define DIM  768
#define OUTC 3072
#define NROW (NB*512)

// ---------------- scratch (__device__ globals; no allocation allowed) -------
__device__ __align__(1024) __half g_ah [(size_t)NB*LA*DIM], g_al [(size_t)NB*LA*DIM];
__device__ __align__(1024) __half g_bh [(size_t)NB*LB*DIM], g_bl [(size_t)NB*LB*DIM];
__device__ __align__(1024) __half g_aTh[(size_t)NB*DIM*LA];
__device__ __align__(1024) __half g_bTh[(size_t)NB*DIM*LB];
__device__ __align__(1024) float g_e[(size_t)NB*LA*LB];
__device__ float g_rpmax[4*NROW], g_rpsum[4*NROW];
__device__ float g_cpmax[4*NROW], g_cpsum[4*NROW];

// ---------------- low-level helpers (portable PTX only) ---------------------
__device__ __forceinline__ uint32_t smem_to_u32(const void* p) {
    uint32_t a;
    asm("{ .reg .u64 t; cvta.to.shared.u64 t, %1; cvt.u32.u64 %0, t; }" : "=r"(a) : "l"(p));
    return a;
}
__device__ __forceinline__ void cp16(uint32_t dst, const void* src) {
    asm volatile("cp.async.cg.shared.global [%0], [%1], 16;" :: "r"(dst), "l"(src));
}
__device__ __forceinline__ void cp_commit() { asm volatile("cp.async.commit_group;"); }
__device__ __forceinline__ void cp_wait1()  { asm volatile("cp.async.wait_group 1;"); }
__device__ __forceinline__ void cp_wait0()  { asm volatile("cp.async.wait_group 0;"); }

__device__ __forceinline__ void ldsm4(uint32_t* r, uint32_t addr) {
    asm volatile("ldmatrix.sync.aligned.m8n8.x4.shared.b16 {%0,%1,%2,%3}, [%4];"
                 : "=r"(r[0]), "=r"(r[1]), "=r"(r[2]), "=r"(r[3]) : "r"(addr));
}
__device__ __forceinline__ void mma_f16(float* c, const uint32_t* a, const uint32_t* b) {
    asm volatile("mma.sync.aligned.m16n8k16.row.col.f32.f16.f16.f32 "
                 "{%0,%1,%2,%3}, {%4,%5,%6,%7}, {%8,%9}, {%0,%1,%2,%3};"
                 : "+f"(c[0]), "+f"(c[1]), "+f"(c[2]), "+f"(c[3])
                 : "r"(a[0]), "r"(a[1]), "r"(a[2]), "r"(a[3]), "r"(b[0]), "r"(b[1]));
}

#define TILE_BYTES 8192            // 128 rows x 32 halfs

__device__ __forceinline__ uint32_t sw_off(int row, int kh) {
    return (uint32_t)(row * 32 + ((kh ^ ((row >> 2) & 1)) << 4));
}

// =============================================================================
// GEMM1: e = (Ah+Al)(Bh+Bl)^T. CTA 128x128, 256 thr (2x4 warps, 64x32 tiles).
// 3-stage cp.async ring, ONE __syncthreads per kt. Stores e + partial stats.
// =============================================================================
#define G1_STAGE (4*TILE_BYTES)                 // 32768
#define G1_SCRATCH 8192
#define G1_SMEM (3*G1_STAGE + G1_SCRATCH + 1024)

__global__ __launch_bounds__(256)
void gemm1_k(const __half* __restrict__ Ah, const __half* __restrict__ Al,
             const __half* __restrict__ Bh, const __half* __restrict__ Bl,
             float* __restrict__ E)
{
    extern __shared__ char smraw[];
    uint32_t sm0 = smem_to_u32(smraw);
    uint32_t smb = (sm0 + 1023u) & ~1023u;
    char* smc = smraw + (smb - sm0);

    const int tid = threadIdx.x;
    const int lid = tid & 31, wid = tid >> 5;
    const int wm = wid >> 2, wn = wid & 3;
    const int g = lid >> 2, t = lid & 3;
    const int z = blockIdx.z, m0 = blockIdx.y * 128, n0 = blockIdx.x * 128;
    const int K = DIM;

    const __half* srcs[4] = {
        Ah + ((size_t)z * LA + m0) * K, Al + ((size_t)z * LA + m0) * K,
        Bh + ((size_t)z * LB + n0) * K, Bl + ((size_t)z * LB + n0) * K };

    const int ar  = (lid & 7) | (((lid >> 3) & 1) << 3);
    const int akh = lid >> 4;
    uint32_t aoff[4];
    #pragma unroll
    for (int i = 0; i < 4; i++)
        aoff[i] = sw_off(wm * 64 + i * 16 + ar, akh);
    const int br  = (lid & 7) | ((lid >> 4) << 3);
    const int bkh = (lid >> 3) & 1;
    uint32_t boff[2];
    #pragma unroll
    for (int j2 = 0; j2 < 2; j2++)
        boff[j2] = sw_off(wn * 32 + j2 * 16 + br, bkh);

    float acc[4][4][4];
    #pragma unroll
    for (int i = 0; i < 4; i++)
        #pragma unroll
        for (int j = 0; j < 4; j++)
            #pragma unroll
            for (int r = 0; r < 4; r++) acc[i][j][r] = 0.f;

    const int nk = K >> 5;   // 24

    auto issue_stage = [&](int s, int kt) {
        uint32_t sb = smb + s * G1_STAGE;
        #pragma unroll
        for (int tl = 0; tl < 4; tl++) {
            #pragma unroll
            for (int it = 0; it < 2; it++) {
                int idx = tid + it * 256;
                int m = idx >> 2, ks = (idx >> 1) & 1, kh = idx & 1;
                cp16(sb + tl * TILE_BYTES + ks * 4096 + sw_off(m, kh),
                     srcs[tl] + (size_t)m * K + kt * 32 + ks * 16 + kh * 8);
            }
        }
        cp_commit();
    };

    issue_stage(0, 0);
    issue_stage(1, 1);

    for (int kt = 0; kt < nk; kt++) {
        if (kt + 1 < nk) cp_wait1(); else cp_wait0();
        __syncthreads();
        if (kt + 2 < nk) issue_stage((kt + 2) % 3, kt + 2);

        uint32_t st = smb + (kt % 3) * G1_STAGE;
        #pragma unroll
        for (int ks = 0; ks < 2; ks++) {
            uint32_t a_h[4][4], a_l[4][4], b_h[4][2], b_l[4][2];
            #pragma unroll
            for (int i = 0; i < 4; i++) {
                ldsm4(a_h[i], st + 0 * TILE_BYTES + ks * 4096 + aoff[i]);
                ldsm4(a_l[i], st + 1 * TILE_BYTES + ks * 4096 + aoff[i]);
            }
            #pragma unroll
            for (int j2 = 0; j2 < 2; j2++) {
                uint32_t rh[4], rl[4];
                ldsm4(rh, st + 2 * TILE_BYTES + ks * 4096 + boff[j2]);
                ldsm4(rl, st + 3 * TILE_BYTES + ks * 4096 + boff[j2]);
                b_h[j2*2+0][0] = rh[0]; b_h[j2*2+0][1] = rh[1];
                b_h[j2*2+1][0] = rh[2]; b_h[j2*2+1][1] = rh[3];
                b_l[j2*2+0][0] = rl[0]; b_l[j2*2+0][1] = rl[1];
                b_l[j2*2+1][0] = rl[2]; b_l[j2*2+1][1] = rl[3];
            }
            #pragma unroll
            for (int i = 0; i < 4; i++)
                #pragma unroll
                for (int j = 0; j < 4; j++) {
                    mma_f16(acc[i][j], a_h[i], b_h[j]);
                    mma_f16(acc[i][j], a_h[i], b_l[j]);
                    mma_f16(acc[i][j], a_l[i], b_h[j]);
                }
        }
    }

    // ---- store e (fp32) ----
    #pragma unroll
    for (int i = 0; i < 4; i++)
        #pragma unroll
        for (int j = 0; j < 4; j++) {
            int n = n0 + wn * 32 + j * 8 + t * 2;
            #pragma unroll
            for (int h = 0; h < 2; h++) {
                int m = m0 + wm * 64 + i * 16 + g + h * 8;
                *(float2*)(E + ((size_t)z * LA + m) * LB + n) =
                    make_float2(acc[i][j][h*2+0], acc[i][j][h*2+1]);
            }
        }

    // ---- partial row/col softmax stats ----
    __syncthreads();
    float* scr   = (float*)(smc + 3 * G1_STAGE);
    float* srmax = scr;            // [128][4]
    float* srsum = scr + 512;      // [128][4]
    float* srm   = scr + 1024;     // [128]
    float* scmax = scr + 1152;     // [128][2]
    float* scsum = scr + 1408;     // [128][2]
    float* scm   = scr + 1664;     // [128]

    #pragma unroll
    for (int i = 0; i < 4; i++)
        #pragma unroll
        for (int h = 0; h < 2; h++) {
            float mv = -3.4e38f;
            #pragma unroll
            for (int j = 0; j < 4; j++) {
                mv = fmaxf(mv, acc[i][j][h*2+0]);
                mv = fmaxf(mv, acc[i][j][h*2+1]);
            }
            mv = fmaxf(mv, __shfl_xor_sync(0xFFFFFFFFu, mv, 1));
            mv = fmaxf(mv, __shfl_xor_sync(0xFFFFFFFFu, mv, 2));
            if (t == 0) srmax[(wm*64 + i*16 + g + h*8) * 4 + wn] = mv;
        }
    __syncthreads();
    if (tid < 128)
        srm[tid] = fmaxf(fmaxf(srmax[tid*4+0], srmax[tid*4+1]),
                         fmaxf(srmax[tid*4+2], srmax[tid*4+3]));
    __syncthreads();
    #pragma unroll
    for (int i = 0; i < 4; i++)
        #pragma unroll
        for (int h = 0; h < 2; h++) {
            int row = wm*64 + i*16 + g + h*8;
            float rm = srm[row], s = 0.f;
            #pragma unroll
            for (int j = 0; j < 4; j++) {
                s += __expf(acc[i][j][h*2+0] - rm);
                s += __expf(acc[i][j][h*2+1] - rm);
            }
            s += __shfl_xor_sync(0xFFFFFFFFu, s, 1);
            s += __shfl_xor_sync(0xFFFFFFFFu, s, 2);
            if (t == 0) srsum[row * 4 + wn] = s;
        }
    __syncthreads();
    if (tid < 128) {
        size_t o = (size_t)blockIdx.x * NROW + z * 512 + m0 + tid;
        g_rpmax[o] = srm[tid];
        g_rpsum[o] = srsum[tid*4+0] + srsum[tid*4+1] + srsum[tid*4+2] + srsum[tid*4+3];
    }

    #pragma unroll
    for (int j = 0; j < 4; j++)
        #pragma unroll
        for (int rl = 0; rl < 2; rl++) {
            float mv = -3.4e38f;
            #pragma unroll
            for (int i = 0; i < 4; i++) {
                mv = fmaxf(mv, acc[i][j][rl]);
                mv = fmaxf(mv, acc[i][j][2+rl]);
            }
            mv = fmaxf(mv, __shfl_xor_sync(0xFFFFFFFFu, mv, 4));
            mv = fmaxf(mv, __shfl_xor_sync(0xFFFFFFFFu, mv, 8));
            mv = fmaxf(mv, __shfl_xor_sync(0xFFFFFFFFu, mv, 16));
            if (g == 0) scmax[(wn*32 + j*8 + t*2 + rl) * 2 + wm] = mv;
        }
    __syncthreads();
    if (tid < 128) scm[tid] = fmaxf(scmax[tid*2], scmax[tid*2+1]);
    __syncthreads();
    #pragma unroll
    for (int j = 0; j < 4; j++)
        #pragma unroll
        for (int rl = 0; rl < 2; rl++) {
            int col = wn*32 + j*8 + t*2 + rl;
            float cm = scm[col], s = 0.f;
            #pragma unroll
            for (int i = 0; i < 4; i++) {
                s += __expf(acc[i][j][rl] - cm);
                s += __expf(acc[i][j][2+rl] - cm);
            }
            s += __shfl_xor_sync(0xFFFFFFFFu, s, 4);
            s += __shfl_xor_sync(0xFFFFFFFFu, s, 8);
            s += __shfl_xor_sync(0xFFFFFFFFu, s, 16);
            if (g == 0) scsum[col * 2 + wm] = s;
        }
    __syncthreads();
    if (tid < 128) {
        size_t o = (size_t)blockIdx.y * NROW + z * 512 + n0 + tid;
        g_cpmax[o] = scm[tid];
        g_cpsum[o] = scsum[tid*2] + scsum[tid*2+1];
    }
}

// =============================================================================
// GEMM_PV: C = P Bh^T. CTA 128x128, 256 thr. A double-buffered (reg-prefetched
// E -> exp -> STS after MMAs), B 3-stage cp.async ring. ONE sync per kt.
// Softmax stats reduced inline from partials (no reduce kernel).
// =============================================================================
#define PV_A_OFF 0                 // 2 stages x 8192
#define PV_B_OFF (2*TILE_BYTES)    // 3 stages x 8192
#define PV_SM    (PV_B_OFF + 3*TILE_BYTES)
#define PV_SMEM  (PV_SM + 1024 + 1024)

template<bool TRANSA>
__global__ __launch_bounds__(256)
void gemm_pv(const float* __restrict__ E, const __half* __restrict__ Bh,
             const float* __restrict__ Obase, float* __restrict__ Out)
{
    const int M = 512, N = DIM, K = 512;
    extern __shared__ char smraw[];
    uint32_t sm0 = smem_to_u32(smraw);
    uint32_t smb = (sm0 + 1023u) & ~1023u;
    char* smc = smraw + (smb - sm0);

    const int tid = threadIdx.x;
    const int lid = tid & 31, wid = tid >> 5;
    const int wm = wid >> 2, wn = wid & 3;
    const int z = blockIdx.z, m0 = blockIdx.y * 128, n0 = blockIdx.x * 128;

    float* sm_m = (float*)(smc + PV_SM);
    float* sm_i = sm_m + 128;
    // inline stats reduction (replaces reduce_stats_k); 4 partials both ways
    if (tid < 128) {
        int row = z * 512 + m0 + tid;
        const float* PM = TRANSA ? g_cpmax : g_rpmax;
        const float* PS = TRANSA ? g_cpsum : g_rpsum;
        float m = -3.4e38f;
        #pragma unroll
        for (int p = 0; p < 4; p++) m = fmaxf(m, PM[p * NROW + row]);
        float s = 0.f;
        #pragma unroll
        for (int p = 0; p < 4; p++) s += PS[p * NROW + row] * __expf(PM[p * NROW + row] - m);
        sm_m[tid] = m;
        sm_i[tid] = 1.f / s;
    }

    const __half* srcB = Bh + ((size_t)z * N + n0) * K;

    const int ar  = (lid & 7) | (((lid >> 3) & 1) << 3);
    const int akh = lid >> 4;
    uint32_t aoff[4];
    #pragma unroll
    for (int i = 0; i < 4; i++)
        aoff[i] = sw_off(wm * 64 + i * 16 + ar, akh);
    const int br  = (lid & 7) | ((lid >> 4) << 3);
    const int bkh = (lid >> 3) & 1;
    uint32_t boff[2];
    #pragma unroll
    for (int j2 = 0; j2 < 2; j2++)
        boff[j2] = sw_off(wn * 32 + j2 * 16 + br, bkh);

    float acc[4][4][4];
    #pragma unroll
    for (int i = 0; i < 4; i++)
        #pragma unroll
        for (int j = 0; j < 4; j++)
            #pragma unroll
            for (int r = 0; r < 4; r++) acc[i][j][r] = 0.f;

    const int nk = K >> 5;   // 16

    auto issueB = [&](int sb, int kt) {
        uint32_t tb = smb + PV_B_OFF + sb * TILE_BYTES;
        #pragma unroll
        for (int it = 0; it < 2; it++) {
            int idx = tid + it * 256;
            int m = idx >> 2, ks = (idx >> 1) & 1, kh = idx & 1;
            cp16(tb + ks * 4096 + sw_off(m, kh),
                 srcB + (size_t)m * K + kt * 32 + ks * 16 + kh * 8);
        }
        cp_commit();
    };

    // load E values for chunk set of iteration kt into registers
    auto loadE = [&](float* ev, int kt) {
        #pragma unroll
        for (int it = 0; it < 2; it++) {
            int c = tid + it * 256;
            if (!TRANSA) {
                int row = c >> 2, kc = c & 3;
                const float* ep = E + ((size_t)z * M + m0 + row) * K + kt * 32 + kc * 8;
                float4 v0 = *(const float4*)(ep);
                float4 v1 = *(const float4*)(ep + 4);
                ev[it*8+0] = v0.x; ev[it*8+1] = v0.y; ev[it*8+2] = v0.z; ev[it*8+3] = v0.w;
                ev[it*8+4] = v1.x; ev[it*8+5] = v1.y; ev[it*8+6] = v1.z; ev[it*8+7] = v1.w;
            } else {
                int col = c & 127, kc = c >> 7;
                #pragma unroll
                for (int ik = 0; ik < 8; ik++)
                    ev[it*8+ik] = E[((size_t)z * 512 + kt * 32 + kc * 8 + ik) * 512 + m0 + col];
            }
        }
    };

    // exp + pack + STS of register E values into A stage sa
    auto storeA = [&](const float* ev, int sa) {
        char* tb = smc + PV_A_OFF + sa * TILE_BYTES;
        #pragma unroll
        for (int it = 0; it < 2; it++) {
            int c = tid + it * 256;
            int row, kc;
            if (!TRANSA) { row = c >> 2;  kc = c & 3; }
            else         { row = c & 127; kc = c >> 7; }
            float rm = sm_m[row], ri = sm_i[row];
            __half2 h0 = __floats2half2_rn(__expf(ev[it*8+0] - rm) * ri, __expf(ev[it*8+1] - rm) * ri);
            __half2 h1 = __floats2half2_rn(__expf(ev[it*8+2] - rm) * ri, __expf(ev[it*8+3] - rm) * ri);
            __half2 h2 = __floats2half2_rn(__expf(ev[it*8+4] - rm) * ri, __expf(ev[it*8+5] - rm) * ri);
            __half2 h3 = __floats2half2_rn(__expf(ev[it*8+6] - rm) * ri, __expf(ev[it*8+7] - rm) * ri);
            uint32_t off = (uint32_t)((kc >> 1) * 4096) + sw_off(row, kc & 1);
            uint4 pk;
            pk.x = *(uint32_t*)&h0; pk.y = *(uint32_t*)&h1;
            pk.z = *(uint32_t*)&h2; pk.w = *(uint32_t*)&h3;
            *(uint4*)(tb + off) = pk;
        }
    };

    // prologue
    issueB(0, 0);
    __syncthreads();          // sm_m/sm_i ready
    {
        float ev0[16];
        loadE(ev0, 0);
        storeA(ev0, 0);
    }
    issueB(1, 1);

    for (int kt = 0; kt < nk; kt++) {
        if (kt + 1 < nk) cp_wait1(); else cp_wait0();
        __syncthreads();      // B(kt) + A(kt) visible; prior-iter reads fenced

        float ev[16];
        if (kt + 1 < nk) loadE(ev, kt + 1);           // LDG overlaps MMAs
        if (kt + 2 < nk) issueB((kt + 2) % 3, kt + 2);

        uint32_t stA = smb + PV_A_OFF + (kt & 1) * TILE_BYTES;
        uint32_t stB = smb + PV_B_OFF + (kt % 3) * TILE_BYTES;
        #pragma unroll
        for (int ks = 0; ks < 2; ks++) {
            uint32_t a_f[4][4], b_h[4][2];
            #pragma unroll
            for (int i = 0; i < 4; i++)
                ldsm4(a_f[i], stA + ks * 4096 + aoff[i]);
            #pragma unroll
            for (int j2 = 0; j2 < 2; j2++) {
                uint32_t rh[4];
                ldsm4(rh, stB + ks * 4096 + boff[j2]);
                b_h[j2*2+0][0] = rh[0]; b_h[j2*2+0][1] = rh[1];
                b_h[j2*2+1][0] = rh[2]; b_h[j2*2+1][1] = rh[3];
            }
            #pragma unroll
            for (int i = 0; i < 4; i++)
                #pragma unroll
                for (int j = 0; j < 4; j++)
                    mma_f16(acc[i][j], a_f[i], b_h[j]);
        }
        if (kt + 1 < nk) storeA(ev, (kt + 1) & 1);
    }

    // ---- ESIM epilogue ----
    const int g = lid >> 2, t = lid & 3;
    #pragma unroll
    for (int i = 0; i < 4; i++)
        #pragma unroll
        for (int j = 0; j < 4; j++) {
            int n = n0 + wn * 32 + j * 8 + t * 2;
            #pragma unroll
            for (int h = 0; h < 2; h++) {
                int m = m0 + wm * 64 + i * 16 + g + h * 8;
                float2 v = make_float2(acc[i][j][h*2+0], acc[i][j][h*2+1]);
                float2 av = *(const float2*)(Obase + ((size_t)z * M + m) * DIM + n);
                float* orow = Out + ((size_t)z * M + m) * OUTC + n;
                *(float2*)(orow)         = av;
                *(float2*)(orow + DIM)   = v;
                *(float2*)(orow + 2*DIM) = make_float2(av.x - v.x, av.y - v.y);
                *(float2*)(orow + 3*DIM) = make_float2(av.x * v.x, av.y * v.y);
            }
        }
}

// ---------------- fp16 split (+ hi transpose) of fp32 input -----------------
__global__ __launch_bounds__(256)
void conv_split_T(const float* __restrict__ X,
                  __half* __restrict__ Xh,  __half* __restrict__ Xl,
                  __half* __restrict__ XTh, int R, int C)
{
    __shared__ __half sh[64][65];
    int z = blockIdx.z, r0 = blockIdx.y * 64, c0 = blockIdx.x * 64;
    #pragma unroll
    for (int it = 0; it < 16; it++) {
        int idx = threadIdx.x + it * 256;
        int i = idx >> 6, j = idx & 63;
        float v = X[((size_t)z * R + r0 + i) * C + c0 + j];
        __half h = __float2half_rn(v);
        __half l = __float2half_rn(v - __half2float(h));
        Xh[((size_t)z * R + r0 + i) * C + c0 + j] = h;
        Xl[((size_t)z * R + r0 + i) * C + c0 + j] = l;
        sh[i][j] = h;
    }
    __syncthreads();
    #pragma unroll
    for (int it = 0; it < 16; it++) {
        int idx = threadIdx.x + it * 256;
        int j = idx >> 6, i = idx & 63;
        XTh[((size_t)z * C + c0 + j) * R + r0 + i] = sh[i][j];
    }
}

// ---------------------------------------------------------------------------
extern "C" void kernel_launch(void* const* d_in, const int* in_sizes, int n_in,
                              void* d_out, int out_size)
{
    const float* a_bar = (const float*)d_in[0];
    const float* b_bar = (const float*)d_in[1];
    float* out = (float*)d_out;
    float* m_a = out;
    float* m_b = out + (size_t)NB * LA * OUTC;

    __half *ah, *al, *bh, *bl, *aTh, *bTh;
    float *pe;
    cudaGetSymbolAddress((void**)&ah,  g_ah);   cudaGetSymbolAddress((void**)&al,  g_al);
    cudaGetSymbolAddress((void**)&bh,  g_bh);   cudaGetSymbolAddress((void**)&bl,  g_bl);
    cudaGetSymbolAddress((void**)&aTh, g_aTh);  cudaGetSymbolAddress((void**)&bTh, g_bTh);
    cudaGetSymbolAddress((void**)&pe,  g_e);

    cudaFuncSetAttribute(gemm1_k, cudaFuncAttributeMaxDynamicSharedMemorySize, G1_SMEM);
    cudaFuncSetAttribute(gemm_pv<false>, cudaFuncAttributeMaxDynamicSharedMemorySize, PV_SMEM);
    cudaFuncSetAttribute(gemm_pv<true>,  cudaFuncAttributeMaxDynamicSharedMemorySize, PV_SMEM);

    // 1) fp16 split + transposed hi copies of inputs
    conv_split_T<<<dim3(DIM/64, LA/64, NB), 256>>>(a_bar, ah, al, aTh, LA, DIM);
    conv_split_T<<<dim3(DIM/64, LB/64, NB), 256>>>(b_bar, bh, bl, bTh, LB, DIM);

    // 2) e = a @ b^T + partial softmax stats
    gemm1_k<<<dim3(LB/128, LA/128, NB), 256, G1_SMEM>>>(ah, al, bh, bl, pe);

    // 3) m_a: softmax_row(e) @ b   (stats reduced inline)
    gemm_pv<false><<<dim3(DIM/128, LA/128, NB), 256, PV_SMEM>>>(pe, bTh, a_bar, m_a);

    // 4) m_b: softmax_col(e)^T @ a (stats reduced inline)
    gemm_pv<true><<<dim3(DIM/128, LB/128, NB), 256, PV_SMEM>>>(pe, aTh, b_bar, m_b);
}

// round 12
// speedup vs baseline: 1.1622x; 1.0248x over previous
#include <cuda_runtime.h>
#include <cuda_fp16.h>
#include <cstdint>

#define NB   32
#define LA   512
#define LB   512
#define DIM  768
#define OUTC 3072
#define NROW (NB*512)

// ---------------- scratch (__device__ globals; no allocation allowed) -------
__device__ __align__(1024) __half g_ah [(size_t)NB*LA*DIM], g_al [(size_t)NB*LA*DIM];
__device__ __align__(1024) __half g_bh [(size_t)NB*LB*DIM], g_bl [(size_t)NB*LB*DIM];
__device__ __align__(1024) __half g_aTh[(size_t)NB*DIM*LA];
__device__ __align__(1024) __half g_bTh[(size_t)NB*DIM*LB];
__device__ __align__(1024) float g_e[(size_t)NB*LA*LB];
__device__ float g_rpmax[4*NROW], g_rpsum[4*NROW];
__device__ float g_cpmax[4*NROW], g_cpsum[4*NROW];

// ---------------- low-level helpers (portable PTX only) ---------------------
__device__ __forceinline__ uint32_t smem_to_u32(const void* p) {
    uint32_t a;
    asm("{ .reg .u64 t; cvta.to.shared.u64 t, %1; cvt.u32.u64 %0, t; }" : "=r"(a) : "l"(p));
    return a;
}
__device__ __forceinline__ void cp16(uint32_t dst, const void* src) {
    asm volatile("cp.async.cg.shared.global [%0], [%1], 16;" :: "r"(dst), "l"(src));
}
__device__ __forceinline__ void cp_commit() { asm volatile("cp.async.commit_group;"); }
__device__ __forceinline__ void cp_wait1()  { asm volatile("cp.async.wait_group 1;"); }
__device__ __forceinline__ void cp_wait0()  { asm volatile("cp.async.wait_group 0;"); }

__device__ __forceinline__ void ldsm4(uint32_t* r, uint32_t addr) {
    asm volatile("ldmatrix.sync.aligned.m8n8.x4.shared.b16 {%0,%1,%2,%3}, [%4];"
                 : "=r"(r[0]), "=r"(r[1]), "=r"(r[2]), "=r"(r[3]) : "r"(addr));
}
__device__ __forceinline__ void mma_f16(float* c, const uint32_t* a, const uint32_t* b) {
    asm volatile("mma.sync.aligned.m16n8k16.row.col.f32.f16.f16.f32 "
                 "{%0,%1,%2,%3}, {%4,%5,%6,%7}, {%8,%9}, {%0,%1,%2,%3};"
                 : "+f"(c[0]), "+f"(c[1]), "+f"(c[2]), "+f"(c[3])
                 : "r"(a[0]), "r"(a[1]), "r"(a[2]), "r"(a[3]), "r"(b[0]), "r"(b[1]));
}
// streaming (evict-first) float2 store — outputs are never re-read
__device__ __forceinline__ void st_cs_f2(float* p, float2 v) {
    asm volatile("st.global.cs.v2.f32 [%0], {%1, %2};" :: "l"(p), "f"(v.x), "f"(v.y) : "memory");
}

#define TILE_BYTES 8192            // 128 rows x 32 halfs

__device__ __forceinline__ uint32_t sw_off(int row, int kh) {
    return (uint32_t)(row * 32 + ((kh ^ ((row >> 2) & 1)) << 4));
}

// =============================================================================
// GEMM1: e = (Ah+Al)(Bh+Bl)^T. CTA 128x128, 256 thr (2x4 warps, 64x32 tiles).
// 3-stage cp.async ring, ONE __syncthreads per kt. Stores e + partial stats.
// =============================================================================
#define G1_STAGE (4*TILE_BYTES)                 // 32768
#define G1_SCRATCH 8192
#define G1_SMEM (3*G1_STAGE + G1_SCRATCH + 1024)

__global__ __launch_bounds__(256)
void gemm1_k(const __half* __restrict__ Ah, const __half* __restrict__ Al,
             const __half* __restrict__ Bh, const __half* __restrict__ Bl,
             float* __restrict__ E)
{
    extern __shared__ char smraw[];
    uint32_t sm0 = smem_to_u32(smraw);
    uint32_t smb = (sm0 + 1023u) & ~1023u;
    char* smc = smraw + (smb - sm0);

    const int tid = threadIdx.x;
    const int lid = tid & 31, wid = tid >> 5;
    const int wm = wid >> 2, wn = wid & 3;
    const int g = lid >> 2, t = lid & 3;
    const int z = blockIdx.z, m0 = blockIdx.y * 128, n0 = blockIdx.x * 128;
    const int K = DIM;

    const __half* srcs[4] = {
        Ah + ((size_t)z * LA + m0) * K, Al + ((size_t)z * LA + m0) * K,
        Bh + ((size_t)z * LB + n0) * K, Bl + ((size_t)z * LB + n0) * K };

    const int ar  = (lid & 7) | (((lid >> 3) & 1) << 3);
    const int akh = lid >> 4;
    uint32_t aoff[4];
    #pragma unroll
    for (int i = 0; i < 4; i++)
        aoff[i] = sw_off(wm * 64 + i * 16 + ar, akh);
    const int br  = (lid & 7) | ((lid >> 4) << 3);
    const int bkh = (lid >> 3) & 1;
    uint32_t boff[2];
    #pragma unroll
    for (int j2 = 0; j2 < 2; j2++)
        boff[j2] = sw_off(wn * 32 + j2 * 16 + br, bkh);

    float acc[4][4][4];
    #pragma unroll
    for (int i = 0; i < 4; i++)
        #pragma unroll
        for (int j = 0; j < 4; j++)
            #pragma unroll
            for (int r = 0; r < 4; r++) acc[i][j][r] = 0.f;

    const int nk = K >> 5;   // 24

    auto issue_stage = [&](int s, int kt) {
        uint32_t sb = smb + s * G1_STAGE;
        #pragma unroll
        for (int tl = 0; tl < 4; tl++) {
            #pragma unroll
            for (int it = 0; it < 2; it++) {
                int idx = tid + it * 256;
                int m = idx >> 2, ks = (idx >> 1) & 1, kh = idx & 1;
                cp16(sb + tl * TILE_BYTES + ks * 4096 + sw_off(m, kh),
                     srcs[tl] + (size_t)m * K + kt * 32 + ks * 16 + kh * 8);
            }
        }
        cp_commit();
    };

    issue_stage(0, 0);
    issue_stage(1, 1);

    for (int kt = 0; kt < nk; kt++) {
        if (kt + 1 < nk) cp_wait1(); else cp_wait0();
        __syncthreads();
        if (kt + 2 < nk) issue_stage((kt + 2) % 3, kt + 2);

        uint32_t st = smb + (kt % 3) * G1_STAGE;
        #pragma unroll
        for (int ks = 0; ks < 2; ks++) {
            uint32_t a_h[4][4], a_l[4][4], b_h[4][2], b_l[4][2];
            #pragma unroll
            for (int i = 0; i < 4; i++) {
                ldsm4(a_h[i], st + 0 * TILE_BYTES + ks * 4096 + aoff[i]);
                ldsm4(a_l[i], st + 1 * TILE_BYTES + ks * 4096 + aoff[i]);
            }
            #pragma unroll
            for (int j2 = 0; j2 < 2; j2++) {
                uint32_t rh[4], rl[4];
                ldsm4(rh, st + 2 * TILE_BYTES + ks * 4096 + boff[j2]);
                ldsm4(rl, st + 3 * TILE_BYTES + ks * 4096 + boff[j2]);
                b_h[j2*2+0][0] = rh[0]; b_h[j2*2+0][1] = rh[1];
                b_h[j2*2+1][0] = rh[2]; b_h[j2*2+1][1] = rh[3];
                b_l[j2*2+0][0] = rl[0]; b_l[j2*2+0][1] = rl[1];
                b_l[j2*2+1][0] = rl[2]; b_l[j2*2+1][1] = rl[3];
            }
            #pragma unroll
            for (int i = 0; i < 4; i++)
                #pragma unroll
                for (int j = 0; j < 4; j++) {
                    mma_f16(acc[i][j], a_h[i], b_h[j]);
                    mma_f16(acc[i][j], a_h[i], b_l[j]);
                    mma_f16(acc[i][j], a_l[i], b_h[j]);
                }
        }
    }

    // ---- store e (fp32; default policy — PV re-reads e through L2) ----
    #pragma unroll
    for (int i = 0; i < 4; i++)
        #pragma unroll
        for (int j = 0; j < 4; j++) {
            int n = n0 + wn * 32 + j * 8 + t * 2;
            #pragma unroll
            for (int h = 0; h < 2; h++) {
                int m = m0 + wm * 64 + i * 16 + g + h * 8;
                *(float2*)(E + ((size_t)z * LA + m) * LB + n) =
                    make_float2(acc[i][j][h*2+0], acc[i][j][h*2+1]);
            }
        }

    // ---- partial row/col softmax stats ----
    __syncthreads();
    float* scr   = (float*)(smc + 3 * G1_STAGE);
    float* srmax = scr;            // [128][4]
    float* srsum = scr + 512;      // [128][4]
    float* srm   = scr + 1024;     // [128]
    float* scmax = scr + 1152;     // [128][2]
    float* scsum = scr + 1408;     // [128][2]
    float* scm   = scr + 1664;     // [128]

    #pragma unroll
    for (int i = 0; i < 4; i++)
        #pragma unroll
        for (int h = 0; h < 2; h++) {
            float mv = -3.4e38f;
            #pragma unroll
            for (int j = 0; j < 4; j++) {
                mv = fmaxf(mv, acc[i][j][h*2+0]);
                mv = fmaxf(mv, acc[i][j][h*2+1]);
            }
            mv = fmaxf(mv, __shfl_xor_sync(0xFFFFFFFFu, mv, 1));
            mv = fmaxf(mv, __shfl_xor_sync(0xFFFFFFFFu, mv, 2));
            if (t == 0) srmax[(wm*64 + i*16 + g + h*8) * 4 + wn] = mv;
        }
    __syncthreads();
    if (tid < 128)
        srm[tid] = fmaxf(fmaxf(srmax[tid*4+0], srmax[tid*4+1]),
                         fmaxf(srmax[tid*4+2], srmax[tid*4+3]));
    __syncthreads();
    #pragma unroll
    for (int i = 0; i < 4; i++)
        #pragma unroll
        for (int h = 0; h < 2; h++) {
            int row = wm*64 + i*16 + g + h*8;
            float rm = srm[row], s = 0.f;
            #pragma unroll
            for (int j = 0; j < 4; j++) {
                s += __expf(acc[i][j][h*2+0] - rm);
                s += __expf(acc[i][j][h*2+1] - rm);
            }
            s += __shfl_xor_sync(0xFFFFFFFFu, s, 1);
            s += __shfl_xor_sync(0xFFFFFFFFu, s, 2);
            if (t == 0) srsum[row * 4 + wn] = s;
        }
    __syncthreads();
    if (tid < 128) {
        size_t o = (size_t)blockIdx.x * NROW + z * 512 + m0 + tid;
        g_rpmax[o] = srm[tid];
        g_rpsum[o] = srsum[tid*4+0] + srsum[tid*4+1] + srsum[tid*4+2] + srsum[tid*4+3];
    }

    #pragma unroll
    for (int j = 0; j < 4; j++)
        #pragma unroll
        for (int rl = 0; rl < 2; rl++) {
            float mv = -3.4e38f;
            #pragma unroll
            for (int i = 0; i < 4; i++) {
                mv = fmaxf(mv, acc[i][j][rl]);
                mv = fmaxf(mv, acc[i][j][2+rl]);
            }
            mv = fmaxf(mv, __shfl_xor_sync(0xFFFFFFFFu, mv, 4));
            mv = fmaxf(mv, __shfl_xor_sync(0xFFFFFFFFu, mv, 8));
            mv = fmaxf(mv, __shfl_xor_sync(0xFFFFFFFFu, mv, 16));
            if (g == 0) scmax[(wn*32 + j*8 + t*2 + rl) * 2 + wm] = mv;
        }
    __syncthreads();
    if (tid < 128) scm[tid] = fmaxf(scmax[tid*2], scmax[tid*2+1]);
    __syncthreads();
    #pragma unroll
    for (int j = 0; j < 4; j++)
        #pragma unroll
        for (int rl = 0; rl < 2; rl++) {
            int col = wn*32 + j*8 + t*2 + rl;
            float cm = scm[col], s = 0.f;
            #pragma unroll
            for (int i = 0; i < 4; i++) {
                s += __expf(acc[i][j][rl] - cm);
                s += __expf(acc[i][j][2+rl] - cm);
            }
            s += __shfl_xor_sync(0xFFFFFFFFu, s, 4);
            s += __shfl_xor_sync(0xFFFFFFFFu, s, 8);
            s += __shfl_xor_sync(0xFFFFFFFFu, s, 16);
            if (g == 0) scsum[col * 2 + wm] = s;
        }
    __syncthreads();
    if (tid < 128) {
        size_t o = (size_t)blockIdx.y * NROW + z * 512 + n0 + tid;
        g_cpmax[o] = scm[tid];
        g_cpsum[o] = scsum[tid*2] + scsum[tid*2+1];
    }
}

// =============================================================================
// GEMM_PV fused: both modes in ONE launch. blockIdx.z: batch = z>>1, mode = z&1
// mode 0: m_a = softmax_row(e) @ b ; mode 1: m_b = softmax_col(e)^T @ a
// CTA 128x128, 256 thr, A double-buffer (reg-prefetched E), B 3-stage ring.
// =============================================================================
#define PV_A_OFF 0                 // 2 stages x 8192
#define PV_B_OFF (2*TILE_BYTES)    // 3 stages x 8192
#define PV_SM    (PV_B_OFF + 3*TILE_BYTES)
#define PV_SMEM  (PV_SM + 1024 + 1024)

__global__ __launch_bounds__(256)
void gemm_pv_fused(const float* __restrict__ E,
                   const __half* __restrict__ bTh, const __half* __restrict__ aTh,
                   const float* __restrict__ a_bar, const float* __restrict__ b_bar,
                   float* __restrict__ m_a, float* __restrict__ m_b)
{
    const int M = 512, N = DIM, K = 512;
    extern __shared__ char smraw[];
    uint32_t sm0 = smem_to_u32(smraw);
    uint32_t smb = (sm0 + 1023u) & ~1023u;
    char* smc = smraw + (smb - sm0);

    const int tid = threadIdx.x;
    const int lid = tid & 31, wid = tid >> 5;
    const int wm = wid >> 2, wn = wid & 3;
    const bool transa = (blockIdx.z & 1);
    const int z = blockIdx.z >> 1;
    const int m0 = blockIdx.y * 128, n0 = blockIdx.x * 128;

    const __half* Bh = transa ? aTh : bTh;
    const float* Obase = transa ? b_bar : a_bar;
    float* Out = transa ? m_b : m_a;

    float* sm_m = (float*)(smc + PV_SM);
    float* sm_i = sm_m + 128;
    if (tid < 128) {
        int row = z * 512 + m0 + tid;
        const float* PM = transa ? g_cpmax : g_rpmax;
        const float* PS = transa ? g_cpsum : g_rpsum;
        float m = -3.4e38f;
        #pragma unroll
        for (int p = 0; p < 4; p++) m = fmaxf(m, PM[p * NROW + row]);
        float s = 0.f;
        #pragma unroll
        for (int p = 0; p < 4; p++) s += PS[p * NROW + row] * __expf(PM[p * NROW + row] - m);
        sm_m[tid] = m;
        sm_i[tid] = 1.f / s;
    }

    const __half* srcB = Bh + ((size_t)z * N + n0) * K;

    const int ar  = (lid & 7) | (((lid >> 3) & 1) << 3);
    const int akh = lid >> 4;
    uint32_t aoff[4];
    #pragma unroll
    for (int i = 0; i < 4; i++)
        aoff[i] = sw_off(wm * 64 + i * 16 + ar, akh);
    const int br  = (lid & 7) | ((lid >> 4) << 3);
    const int bkh = (lid >> 3) & 1;
    uint32_t boff[2];
    #pragma unroll
    for (int j2 = 0; j2 < 2; j2++)
        boff[j2] = sw_off(wn * 32 + j2 * 16 + br, bkh);

    float acc[4][4][4];
    #pragma unroll
    for (int i = 0; i < 4; i++)
        #pragma unroll
        for (int j = 0; j < 4; j++)
            #pragma unroll
            for (int r = 0; r < 4; r++) acc[i][j][r] = 0.f;

    const int nk = K >> 5;   // 16

    auto issueB = [&](int sb, int kt) {
        uint32_t tb = smb + PV_B_OFF + sb * TILE_BYTES;
        #pragma unroll
        for (int it = 0; it < 2; it++) {
            int idx = tid + it * 256;
            int m = idx >> 2, ks = (idx >> 1) & 1, kh = idx & 1;
            cp16(tb + ks * 4096 + sw_off(m, kh),
                 srcB + (size_t)m * K + kt * 32 + ks * 16 + kh * 8);
        }
        cp_commit();
    };

    auto loadE = [&](float* ev, int kt) {
        #pragma unroll
        for (int it = 0; it < 2; it++) {
            int c = tid + it * 256;
            if (!transa) {
                int row = c >> 2, kc = c & 3;
                const float* ep = E + ((size_t)z * M + m0 + row) * K + kt * 32 + kc * 8;
                float4 v0 = *(const float4*)(ep);
                float4 v1 = *(const float4*)(ep + 4);
                ev[it*8+0] = v0.x; ev[it*8+1] = v0.y; ev[it*8+2] = v0.z; ev[it*8+3] = v0.w;
                ev[it*8+4] = v1.x; ev[it*8+5] = v1.y; ev[it*8+6] = v1.z; ev[it*8+7] = v1.w;
            } else {
                int col = c & 127, kc = c >> 7;
                #pragma unroll
                for (int ik = 0; ik < 8; ik++)
                    ev[it*8+ik] = E[((size_t)z * 512 + kt * 32 + kc * 8 + ik) * 512 + m0 + col];
            }
        }
    };

    auto storeA = [&](const float* ev, int sa) {
        char* tb = smc + PV_A_OFF + sa * TILE_BYTES;
        #pragma unroll
        for (int it = 0; it < 2; it++) {
            int c = tid + it * 256;
            int row, kc;
            if (!transa) { row = c >> 2;  kc = c & 3; }
            else         { row = c & 127; kc = c >> 7; }
            float rm = sm_m[row], ri = sm_i[row];
            __half2 h0 = __floats2half2_rn(__expf(ev[it*8+0] - rm) * ri, __expf(ev[it*8+1] - rm) * ri);
            __half2 h1 = __floats2half2_rn(__expf(ev[it*8+2] - rm) * ri, __expf(ev[it*8+3] - rm) * ri);
            __half2 h2 = __floats2half2_rn(__expf(ev[it*8+4] - rm) * ri, __expf(ev[it*8+5] - rm) * ri);
            __half2 h3 = __floats2half2_rn(__expf(ev[it*8+6] - rm) * ri, __expf(ev[it*8+7] - rm) * ri);
            uint32_t off = (uint32_t)((kc >> 1) * 4096) + sw_off(row, kc & 1);
            uint4 pk;
            pk.x = *(uint32_t*)&h0; pk.y = *(uint32_t*)&h1;
            pk.z = *(uint32_t*)&h2; pk.w = *(uint32_t*)&h3;
            *(uint4*)(tb + off) = pk;
        }
    };

    // prologue
    issueB(0, 0);
    __syncthreads();          // sm_m/sm_i ready
    {
        float ev0[16];
        loadE(ev0, 0);
        storeA(ev0, 0);
    }
    issueB(1, 1);

    for (int kt = 0; kt < nk; kt++) {
        if (kt + 1 < nk) cp_wait1(); else cp_wait0();
        __syncthreads();

        float ev[16];
        if (kt + 1 < nk) loadE(ev, kt + 1);
        if (kt + 2 < nk) issueB((kt + 2) % 3, kt + 2);

        uint32_t stA = smb + PV_A_OFF + (kt & 1) * TILE_BYTES;
        uint32_t stB = smb + PV_B_OFF + (kt % 3) * TILE_BYTES;
        #pragma unroll
        for (int ks = 0; ks < 2; ks++) {
            uint32_t a_f[4][4], b_h[4][2];
            #pragma unroll
            for (int i = 0; i < 4; i++)
                ldsm4(a_f[i], stA + ks * 4096 + aoff[i]);
            #pragma unroll
            for (int j2 = 0; j2 < 2; j2++) {
                uint32_t rh[4];
                ldsm4(rh, stB + ks * 4096 + boff[j2]);
                b_h[j2*2+0][0] = rh[0]; b_h[j2*2+0][1] = rh[1];
                b_h[j2*2+1][0] = rh[2]; b_h[j2*2+1][1] = rh[3];
            }
            #pragma unroll
            for (int i = 0; i < 4; i++)
                #pragma unroll
                for (int j = 0; j < 4; j++)
                    mma_f16(acc[i][j], a_f[i], b_h[j]);
        }
        if (kt + 1 < nk) storeA(ev, (kt + 1) & 1);
    }

    // ---- ESIM epilogue (streaming stores) ----
    const int g = lid >> 2, t = lid & 3;
    #pragma unroll
    for (int i = 0; i < 4; i++)
        #pragma unroll
        for (int j = 0; j < 4; j++) {
            int n = n0 + wn * 32 + j * 8 + t * 2;
            #pragma unroll
            for (int h = 0; h < 2; h++) {
                int m = m0 + wm * 64 + i * 16 + g + h * 8;
                float2 v = make_float2(acc[i][j][h*2+0], acc[i][j][h*2+1]);
                float2 av = *(const float2*)(Obase + ((size_t)z * M + m) * DIM + n);
                float* orow = Out + ((size_t)z * M + m) * OUTC + n;
                st_cs_f2(orow,           av);
                st_cs_f2(orow + DIM,     v);
                st_cs_f2(orow + 2*DIM,   make_float2(av.x - v.x, av.y - v.y));
                st_cs_f2(orow + 3*DIM,   make_float2(av.x * v.x, av.y * v.y));
            }
        }
}

// ---------------- fp16 split (+ hi transpose) of fp32 input -----------------
__global__ __launch_bounds__(256)
void conv_split_T(const float* __restrict__ X,
                  __half* __restrict__ Xh,  __half* __restrict__ Xl,
                  __half* __restrict__ XTh, int R, int C)
{
    __shared__ __half sh[64][65];
    int z = blockIdx.z, r0 = blockIdx.y * 64, c0 = blockIdx.x * 64;
    #pragma unroll
    for (int it = 0; it < 16; it++) {
        int idx = threadIdx.x + it * 256;
        int i = idx >> 6, j = idx & 63;
        float v = X[((size_t)z * R + r0 + i) * C + c0 + j];
        __half h = __float2half_rn(v);
        __half l = __float2half_rn(v - __half2float(h));
        Xh[((size_t)z * R + r0 + i) * C + c0 + j] = h;
        Xl[((size_t)z * R + r0 + i) * C + c0 + j] = l;
        sh[i][j] = h;
    }
    __syncthreads();
    #pragma unroll
    for (int it = 0; it < 16; it++) {
        int idx = threadIdx.x + it * 256;
        int j = idx >> 6, i = idx & 63;
        XTh[((size_t)z * C + c0 + j) * R + r0 + i] = sh[i][j];
    }
}

// ---------------------------------------------------------------------------
extern "C" void kernel_launch(void* const* d_in, const int* in_sizes, int n_in,
                              void* d_out, int out_size)
{
    const float* a_bar = (const float*)d_in[0];
    const float* b_bar = (const float*)d_in[1];
    float* out = (float*)d_out;
    float* m_a = out;
    float* m_b = out + (size_t)NB * LA * OUTC;

    __half *ah, *al, *bh, *bl, *aTh, *bTh;
    float *pe;
    cudaGetSymbolAddress((void**)&ah,  g_ah);   cudaGetSymbolAddress((void**)&al,  g_al);
    cudaGetSymbolAddress((void**)&bh,  g_bh);   cudaGetSymbolAddress((void**)&bl,  g_bl);
    cudaGetSymbolAddress((void**)&aTh, g_aTh);  cudaGetSymbolAddress((void**)&bTh, g_bTh);
    cudaGetSymbolAddress((void**)&pe,  g_e);

    cudaFuncSetAttribute(gemm1_k, cudaFuncAttributeMaxDynamicSharedMemorySize, G1_SMEM);
    cudaFuncSetAttribute(gemm_pv_fused, cudaFuncAttributeMaxDynamicSharedMemorySize, PV_SMEM);

    // 1) fp16 split + transposed hi copies of inputs
    conv_split_T<<<dim3(DIM/64, LA/64, NB), 256>>>(a_bar, ah, al, aTh, LA, DIM);
    conv_split_T<<<dim3(DIM/64, LB/64, NB), 256>>>(b_bar, bh, bl, bTh, LB, DIM);

    // 2) e = a @ b^T + partial softmax stats
    gemm1_k<<<dim3(LB/128, LA/128, NB), 256, G1_SMEM>>>(ah, al, bh, bl, pe);

    // 3) both PV GEMMs in one fused launch (mode = blockIdx.z & 1)
    gemm_pv_fused<<<dim3(DIM/128, 512/128, 2*NB), 256, PV_SMEM>>>(
        pe, bTh, aTh, a_bar, b_bar, m_a, m_b);
}